// round 1
// baseline (speedup 1.0000x reference)
#include <cuda_runtime.h>

// GraphConv: out = segment_sum(x[src], dst, N) @ W2 + b2
//          = segment_sum((x @ W2)[src], dst, N) + b2   (linearity)
// Pipeline: detect idx dtype -> init out=b2 -> y = x@W2 -> scatter-add y[src] into out[dst]

constexpr int NN = 50000;
constexpr int FD = 128;
constexpr int NE = 600000;

__device__ __align__(16) float g_y[(size_t)NN * FD];
__device__ int g_idx64;

// ---------------------------------------------------------------------------
// Detect whether edge_index is int64 (odd 32-bit words all zero) or int32.
// ---------------------------------------------------------------------------
__global__ void detect_kernel(const unsigned int* __restrict__ w) {
    __shared__ int found;
    if (threadIdx.x == 0) found = 0;
    __syncthreads();
    unsigned int v = 0;
    for (int i = threadIdx.x; i < 1024; i += 256) v |= w[2 * i + 1];
    if (v) atomicOr(&found, 1);
    __syncthreads();
    if (threadIdx.x == 0) g_idx64 = found ? 0 : 1;
}

// ---------------------------------------------------------------------------
// out[n][c] = b2[c]  (also clears the 0xAA poison)
// ---------------------------------------------------------------------------
__global__ void init_kernel(const float* __restrict__ b2, float* __restrict__ out) {
    int i = blockIdx.x * blockDim.x + threadIdx.x;   // float4 index
    if (i < NN * FD / 4) {
        float4 v = reinterpret_cast<const float4*>(b2)[i & 31];
        reinterpret_cast<float4*>(out)[i] = v;
    }
}

// ---------------------------------------------------------------------------
// y = x @ W2.  Block: 64 rows x 128 cols, 256 threads, each thread 4x8 outputs.
// Smem: W2 full (64KB) + x tile (64x132 padded, 33KB) = 99328 B dynamic.
// ---------------------------------------------------------------------------
constexpr int GEMM_SMEM = (FD * FD + 64 * 132) * 4;

__global__ __launch_bounds__(256, 2) void gemm_kernel(const float* __restrict__ x,
                                                      const float* __restrict__ W) {
    extern __shared__ float smem[];
    float* Ws = smem;                 // [128][128]
    float* xs = smem + FD * FD;       // [64][132]  (pad 132 -> conflict-free row reads)
    const int XS_LD = 132;

    int tid = threadIdx.x;
    int row0 = blockIdx.x * 64;

    // Load W2 (4096 float4, coalesced)
    {
        const float4* Wg = reinterpret_cast<const float4*>(W);
        float4* Wsv = reinterpret_cast<float4*>(Ws);
#pragma unroll
        for (int i = 0; i < 16; i++) Wsv[tid + 256 * i] = Wg[tid + 256 * i];
    }
    // Load x tile (64 rows x 32 float4)
    {
        const float4* xg = reinterpret_cast<const float4*>(x);
#pragma unroll
        for (int i = 0; i < 8; i++) {
            int idx = tid + 256 * i;       // 0..2047
            int r = idx >> 5;
            int c = idx & 31;
            float4 v = make_float4(0.f, 0.f, 0.f, 0.f);
            if (row0 + r < NN) v = xg[(size_t)(row0 + r) * 32 + c];
            *reinterpret_cast<float4*>(xs + r * XS_LD + c * 4) = v;
        }
    }
    __syncthreads();

    int tx = tid & 15;   // col group: cols tx*4..tx*4+3 and tx*4+64..tx*4+67
    int ty = tid >> 4;   // rows ty + 16*i, i=0..3

    float acc[4][8];
#pragma unroll
    for (int i = 0; i < 4; i++)
#pragma unroll
        for (int j = 0; j < 8; j++) acc[i][j] = 0.f;

#pragma unroll 8
    for (int k = 0; k < FD; k++) {
        float4 w0 = *reinterpret_cast<const float4*>(Ws + k * FD + tx * 4);
        float4 w1 = *reinterpret_cast<const float4*>(Ws + k * FD + tx * 4 + 64);
        float xv[4];
#pragma unroll
        for (int i = 0; i < 4; i++) xv[i] = xs[(ty + 16 * i) * XS_LD + k];
#pragma unroll
        for (int i = 0; i < 4; i++) {
            acc[i][0] += xv[i] * w0.x;
            acc[i][1] += xv[i] * w0.y;
            acc[i][2] += xv[i] * w0.z;
            acc[i][3] += xv[i] * w0.w;
            acc[i][4] += xv[i] * w1.x;
            acc[i][5] += xv[i] * w1.y;
            acc[i][6] += xv[i] * w1.z;
            acc[i][7] += xv[i] * w1.w;
        }
    }

#pragma unroll
    for (int i = 0; i < 4; i++) {
        int r = row0 + ty + 16 * i;
        if (r < NN) {
            float4 v0 = make_float4(acc[i][0], acc[i][1], acc[i][2], acc[i][3]);
            float4 v1 = make_float4(acc[i][4], acc[i][5], acc[i][6], acc[i][7]);
            *reinterpret_cast<float4*>(g_y + (size_t)r * FD + tx * 4) = v0;
            *reinterpret_cast<float4*>(g_y + (size_t)r * FD + tx * 4 + 64) = v1;
        }
    }
}

// ---------------------------------------------------------------------------
// Scatter: one warp per edge; out[dst] += y[src] via red.global.add.v4.f32
// ---------------------------------------------------------------------------
__global__ void scatter_kernel(const void* __restrict__ ei_raw, float* __restrict__ out) {
    int gt = blockIdx.x * blockDim.x + threadIdx.x;
    int e = gt >> 5;
    if (e >= NE) return;
    int lane = gt & 31;

    int src, dst;
    if (g_idx64) {
        const long long* ei = reinterpret_cast<const long long*>(ei_raw);
        src = (int)ei[e];
        dst = (int)ei[NE + e];
    } else {
        const int* ei = reinterpret_cast<const int*>(ei_raw);
        src = ei[e];
        dst = ei[NE + e];
    }

    float4 v = *reinterpret_cast<const float4*>(g_y + (size_t)src * FD + lane * 4);
    float* op = out + (size_t)dst * FD + lane * 4;
    asm volatile("red.global.add.v4.f32 [%0], {%1, %2, %3, %4};"
                 :: "l"(op), "f"(v.x), "f"(v.y), "f"(v.z), "f"(v.w)
                 : "memory");
}

// ---------------------------------------------------------------------------
extern "C" void kernel_launch(void* const* d_in, const int* in_sizes, int n_in,
                              void* d_out, int out_size) {
    const float* x  = (const float*)d_in[0];
    const void*  ei = d_in[1];
    // d_in[2]=edge_weight, d_in[3]=W1, d_in[4]=b1 : dead in reference
    const float* W2 = (const float*)d_in[5];
    const float* b2 = (const float*)d_in[6];
    float* out = (float*)d_out;

    cudaFuncSetAttribute(gemm_kernel, cudaFuncAttributeMaxDynamicSharedMemorySize, GEMM_SMEM);

    detect_kernel<<<1, 256>>>((const unsigned int*)ei);
    init_kernel<<<(NN * FD / 4 + 255) / 256, 256>>>(b2, out);
    gemm_kernel<<<(NN + 63) / 64, 256, GEMM_SMEM>>>(x, W2);
    scatter_kernel<<<(NE * 32 + 255) / 256, 256>>>(ei, out);
}

// round 2
// speedup vs baseline: 1.4148x; 1.4148x over previous
#include <cuda_runtime.h>

// GraphConv: out = segment_sum(x[src], dst, N) @ W2 + b2
// Plan: bucketed counting-sort of edges by dst (cap 64/node, overflow list),
//       warp-per-node register gather of x rows -> agg, then GEMM agg@W2+b2 -> out.

constexpr int NN = 50000;
constexpr int FD = 128;
constexpr int NE = 600000;
constexpr int CAP = 64;
constexpr int OVF_CAP = 8192;

__device__ __align__(16) float g_agg[(size_t)NN * FD];
__device__ int g_cnt[NN];
__device__ int g_adj[(size_t)NN * CAP];
__device__ int g_ovf[OVF_CAP * 2];
__device__ int g_ovf_cnt;
__device__ int g_idx64;

// ---------------------------------------------------------------------------
// Zero counters; block 0 also detects whether edge_index is int64 or int32.
// ---------------------------------------------------------------------------
__global__ void zero_detect_kernel(const unsigned int* __restrict__ w) {
    int i = blockIdx.x * blockDim.x + threadIdx.x;
    if (i < NN) g_cnt[i] = 0;
    if (blockIdx.x == 0) {
        if (threadIdx.x == 0) g_ovf_cnt = 0;
        __shared__ int found;
        if (threadIdx.x == 0) found = 0;
        __syncthreads();
        unsigned int v = 0;
        for (int j = threadIdx.x; j < 1024; j += 256) v |= w[2 * j + 1];
        if (v) atomicOr(&found, 1);
        __syncthreads();
        if (threadIdx.x == 0) g_idx64 = found ? 0 : 1;
    }
}

// ---------------------------------------------------------------------------
// Counting-sort fill: adj[dst*CAP + p] = src. Overflow -> (src,dst) list.
// ---------------------------------------------------------------------------
__global__ void fill_kernel(const void* __restrict__ ei_raw) {
    int e = blockIdx.x * blockDim.x + threadIdx.x;
    if (e >= NE) return;
    int src, dst;
    if (g_idx64) {
        const long long* ei = reinterpret_cast<const long long*>(ei_raw);
        src = (int)ei[e];
        dst = (int)ei[NE + e];
    } else {
        const int* ei = reinterpret_cast<const int*>(ei_raw);
        src = ei[e];
        dst = ei[NE + e];
    }
    int p = atomicAdd(&g_cnt[dst], 1);
    if (p < CAP) {
        g_adj[dst * CAP + p] = src;
    } else {
        int q = atomicAdd(&g_ovf_cnt, 1);
        if (q < OVF_CAP) { g_ovf[2 * q] = src; g_ovf[2 * q + 1] = dst; }
    }
}

// ---------------------------------------------------------------------------
// Gather: one warp per node. agg[n] = sum_{e: dst=n} x[src_e]. Unroll-4 MLP.
// ---------------------------------------------------------------------------
__global__ __launch_bounds__(128) void gather_kernel(const float* __restrict__ x) {
    int n = blockIdx.x * 4 + (threadIdx.x >> 5);
    if (n >= NN) return;
    int lane = threadIdx.x & 31;

    int deg = g_cnt[n];
    if (deg > CAP) deg = CAP;
    const int* adjp = g_adj + (size_t)n * CAP;
    int a0 = adjp[lane];
    int a1 = adjp[lane + 32];

    float4 acc = make_float4(0.f, 0.f, 0.f, 0.f);
    int j = 0;
    for (; j + 4 <= deg; j += 4) {
        int base = (j < 32) ? a0 : a1;   // 4 | 32 so no straddle
        int s0 = __shfl_sync(0xffffffffu, base, (j + 0) & 31);
        int s1 = __shfl_sync(0xffffffffu, base, (j + 1) & 31);
        int s2 = __shfl_sync(0xffffffffu, base, (j + 2) & 31);
        int s3 = __shfl_sync(0xffffffffu, base, (j + 3) & 31);
        float4 v0 = *(reinterpret_cast<const float4*>(x + (size_t)s0 * FD) + lane);
        float4 v1 = *(reinterpret_cast<const float4*>(x + (size_t)s1 * FD) + lane);
        float4 v2 = *(reinterpret_cast<const float4*>(x + (size_t)s2 * FD) + lane);
        float4 v3 = *(reinterpret_cast<const float4*>(x + (size_t)s3 * FD) + lane);
        acc.x += v0.x + v1.x + v2.x + v3.x;
        acc.y += v0.y + v1.y + v2.y + v3.y;
        acc.z += v0.z + v1.z + v2.z + v3.z;
        acc.w += v0.w + v1.w + v2.w + v3.w;
    }
    for (; j < deg; j++) {
        int base = (j < 32) ? a0 : a1;
        int s = __shfl_sync(0xffffffffu, base, j & 31);
        float4 v = *(reinterpret_cast<const float4*>(x + (size_t)s * FD) + lane);
        acc.x += v.x; acc.y += v.y; acc.z += v.z; acc.w += v.w;
    }
    *(reinterpret_cast<float4*>(g_agg + (size_t)n * FD) + lane) = acc;
}

// ---------------------------------------------------------------------------
// Overflow fixup (normally 0 entries): agg[dst] += x[src] via red.v4
// ---------------------------------------------------------------------------
__global__ void ovf_kernel(const float* __restrict__ x) {
    int cnt = g_ovf_cnt;
    if (cnt > OVF_CAP) cnt = OVF_CAP;
    int lane = threadIdx.x & 31;
    int warp = (blockIdx.x * blockDim.x + threadIdx.x) >> 5;
    int nwarp = (gridDim.x * blockDim.x) >> 5;
    for (int q = warp; q < cnt; q += nwarp) {
        int src = g_ovf[2 * q];
        int dst = g_ovf[2 * q + 1];
        float4 v = *(reinterpret_cast<const float4*>(x + (size_t)src * FD) + lane);
        float* op = g_agg + (size_t)dst * FD + lane * 4;
        asm volatile("red.global.add.v4.f32 [%0], {%1, %2, %3, %4};"
                     :: "l"(op), "f"(v.x), "f"(v.y), "f"(v.z), "f"(v.w)
                     : "memory");
    }
}

// ---------------------------------------------------------------------------
// out = agg @ W2 + b2. Block: 64 rows x 128 cols, 256 threads, 4x8 per thread.
// ---------------------------------------------------------------------------
constexpr int GEMM_SMEM = (FD * FD + 64 * 132) * 4;

__global__ __launch_bounds__(256, 2) void gemm_kernel(const float* __restrict__ W,
                                                      const float* __restrict__ b2,
                                                      float* __restrict__ out) {
    extern __shared__ float smem[];
    float* Ws = smem;                 // [128][128]
    float* xs = smem + FD * FD;       // [64][132]
    const int XS_LD = 132;

    int tid = threadIdx.x;
    int row0 = blockIdx.x * 64;

    {
        const float4* Wg = reinterpret_cast<const float4*>(W);
        float4* Wsv = reinterpret_cast<float4*>(Ws);
#pragma unroll
        for (int i = 0; i < 16; i++) Wsv[tid + 256 * i] = Wg[tid + 256 * i];
    }
    {
        const float4* xg = reinterpret_cast<const float4*>(g_agg);
#pragma unroll
        for (int i = 0; i < 8; i++) {
            int idx = tid + 256 * i;
            int r = idx >> 5;
            int c = idx & 31;
            float4 v = make_float4(0.f, 0.f, 0.f, 0.f);
            if (row0 + r < NN) v = xg[(size_t)(row0 + r) * 32 + c];
            *reinterpret_cast<float4*>(xs + r * XS_LD + c * 4) = v;
        }
    }
    __syncthreads();

    int tx = tid & 15;
    int ty = tid >> 4;

    float acc[4][8];
#pragma unroll
    for (int i = 0; i < 4; i++)
#pragma unroll
        for (int j = 0; j < 8; j++) acc[i][j] = 0.f;

#pragma unroll 8
    for (int k = 0; k < FD; k++) {
        float4 w0 = *reinterpret_cast<const float4*>(Ws + k * FD + tx * 4);
        float4 w1 = *reinterpret_cast<const float4*>(Ws + k * FD + tx * 4 + 64);
        float xv[4];
#pragma unroll
        for (int i = 0; i < 4; i++) xv[i] = xs[(ty + 16 * i) * XS_LD + k];
#pragma unroll
        for (int i = 0; i < 4; i++) {
            acc[i][0] += xv[i] * w0.x;
            acc[i][1] += xv[i] * w0.y;
            acc[i][2] += xv[i] * w0.z;
            acc[i][3] += xv[i] * w0.w;
            acc[i][4] += xv[i] * w1.x;
            acc[i][5] += xv[i] * w1.y;
            acc[i][6] += xv[i] * w1.z;
            acc[i][7] += xv[i] * w1.w;
        }
    }

    float4 bias0 = *reinterpret_cast<const float4*>(b2 + tx * 4);
    float4 bias1 = *reinterpret_cast<const float4*>(b2 + tx * 4 + 64);
#pragma unroll
    for (int i = 0; i < 4; i++) {
        int r = row0 + ty + 16 * i;
        if (r < NN) {
            float4 v0 = make_float4(acc[i][0] + bias0.x, acc[i][1] + bias0.y,
                                    acc[i][2] + bias0.z, acc[i][3] + bias0.w);
            float4 v1 = make_float4(acc[i][4] + bias1.x, acc[i][5] + bias1.y,
                                    acc[i][6] + bias1.z, acc[i][7] + bias1.w);
            *reinterpret_cast<float4*>(out + (size_t)r * FD + tx * 4) = v0;
            *reinterpret_cast<float4*>(out + (size_t)r * FD + tx * 4 + 64) = v1;
        }
    }
}

// ---------------------------------------------------------------------------
extern "C" void kernel_launch(void* const* d_in, const int* in_sizes, int n_in,
                              void* d_out, int out_size) {
    const float* x  = (const float*)d_in[0];
    const void*  ei = d_in[1];
    // d_in[2]=edge_weight, d_in[3]=W1, d_in[4]=b1 : dead in reference
    const float* W2 = (const float*)d_in[5];
    const float* b2 = (const float*)d_in[6];
    float* out = (float*)d_out;

    cudaFuncSetAttribute(gemm_kernel, cudaFuncAttributeMaxDynamicSharedMemorySize, GEMM_SMEM);

    zero_detect_kernel<<<(NN + 255) / 256, 256>>>((const unsigned int*)ei);
    fill_kernel<<<(NE + 255) / 256, 256>>>(ei);
    gather_kernel<<<(NN + 3) / 4, 128>>>(x);
    ovf_kernel<<<8, 256>>>(x);
    gemm_kernel<<<(NN + 63) / 64, 256, GEMM_SMEM>>>(W2, b2, out);
}